// round 6
// baseline (speedup 1.0000x reference)
#include <cuda_runtime.h>
#include <cuda_bf16.h>
#include <mma.h>
#include <cstdint>
#include <math.h>

using namespace nvcuda;

#define Bb 256
#define Ll 256
#define Dd 768
#define Hh 1024
#define Tt 32
#define KV (3*Dd)   // 2304
#define Gg (4*Hh)   // 4096
#define NL (3*Ll)   // 768
#define KCH 64      // K elems per smem chunk
#define LDS 72      // padded smem stride (elems), 144 B

// ======================= device scratch (no allocs allowed) =======================
__device__ float g_c[Bb*Hh];
__device__ float g_att[Bb*NL];
__device__ float g_gates[Bb*Gg];
__device__ float g_biasG[Gg];
__device__ float g_biasA[NL];
__device__ __align__(16) __nv_bfloat16 g_hh_[Bb*Hh], g_hl_[Bb*Hh];
__device__ __align__(16) __nv_bfloat16 g_vh_[Bb*KV], g_vl_[Bb*KV];
__device__ __align__(16) __nv_bfloat16 g_Wah[NL*Hh],  g_Wal[NL*Hh];
__device__ __align__(16) __nv_bfloat16 g_Wihh[Gg*KV], g_Wihl[Gg*KV];
__device__ __align__(16) __nv_bfloat16 g_Whhh[Gg*Hh], g_Whhl[Gg*Hh];

__device__ __forceinline__ void split2(float a, __nv_bfloat16* hi, __nv_bfloat16* lo) {
    __nv_bfloat16 h = __float2bfloat16_rn(a);
    *hi = h;
    *lo = __float2bfloat16_rn(a - __bfloat162float(h));
}

__device__ __forceinline__ uint32_t smem_u32(const void* p) {
    uint32_t a;
    asm("{ .reg .u64 t; cvta.to.shared.u64 t, %1; cvt.u32.u64 %0, t; }" : "=r"(a) : "l"(p));
    return a;
}
__device__ __forceinline__ void cp16(uint32_t s, const void* g) {
    asm volatile("cp.async.cg.shared.global [%0], [%1], 16;" :: "r"(s), "l"(g));
}
#define CP_COMMIT() asm volatile("cp.async.commit_group;" ::: "memory")
#define CP_WAIT(n)  asm volatile("cp.async.wait_group %0;" :: "n"(n) : "memory")

// ======================= prep kernels =======================
__global__ void split_kernel(const float* __restrict__ src, __nv_bfloat16* __restrict__ hi,
                             __nv_bfloat16* __restrict__ lo, int n) {
    for (int i = blockIdx.x * blockDim.x + threadIdx.x; i < n; i += gridDim.x * blockDim.x)
        split2(src[i], &hi[i], &lo[i]);
}

__global__ void bias_prep_kernel(const float* __restrict__ b_ih, const float* __restrict__ b_hh,
                                 const float* __restrict__ b1, const float* __restrict__ b2,
                                 const float* __restrict__ b3) {
    int j = blockIdx.x * blockDim.x + threadIdx.x;
    if (j < Gg) g_biasG[j] = b_ih[j] + b_hh[j];
    if (j < NL) g_biasA[j] = (j < Ll) ? b1[j] : (j < 2*Ll) ? b2[j - Ll] : b3[j - 2*Ll];
}

__global__ void init_kernel(const float* __restrict__ h0, const float* __restrict__ c0) {
    int i = blockIdx.x * blockDim.x + threadIdx.x;
    if (i < Bb*Hh) { split2(h0[i], &g_hh_[i], &g_hl_[i]); g_c[i] = c0[i]; }
}

// ======================= split-bf16 WMMA GEMM =======================
// C[256, Ntot] = (Ah+Al)[256, Ktot] @ (Wh+Wl)[Ntot, Ktot]^T  (no bias; consumers add it)
// MODE 0: logits (A=h, K=1024, W=Wa, C=g_att, BM=64)
// MODE 1: gates  (A=[v|h], K=2304+1024, W=[Wih|Whh], C=g_gates, BM=128)
template <int MODE>
__global__ void __launch_bounds__(256, 1) gemm_split_kernel() {
    constexpr int BM = MODE ? 128 : 64;
    constexpr int BN = 64;
    constexpr int FM = MODE ? 2 : 1;        // 16x16 frags per warp (m)
    constexpr int FN = 2;                    // frags per warp (n)
    constexpr int K1 = MODE ? KV : Hh;
    constexpr int K2 = MODE ? Hh : 0;
    constexpr int NCH = (K1 + K2) / KCH;
    constexpr int Ntot = MODE ? Gg : NL;
    constexpr int SS = (2*BM + 2*BN) * LDS * 2;     // bytes per stage
    constexpr int AOFF = BM * LDS * 2;               // Al offset within stage
    constexpr int BOFF = 2 * BM * LDS * 2;           // Bh offset
    constexpr int BLOFF = BOFF + BN * LDS * 2;       // Bl offset

    extern __shared__ __align__(16) char smem[];
    const uint32_t sb = smem_u32(smem);

    const int tid = threadIdx.x;
    const int wid = tid >> 5;
    const int wm = wid >> 1;                 // 0..3
    const int wn = wid & 1;                  // 0..1
    const int col0 = blockIdx.x * BN;
    const int row0 = blockIdx.y * BM;

    const __nv_bfloat16* A1h = MODE ? g_vh_ : g_hh_;
    const __nv_bfloat16* A1l = MODE ? g_vl_ : g_hl_;
    const __nv_bfloat16* W1h = MODE ? g_Wihh : g_Wah;
    const __nv_bfloat16* W1l = MODE ? g_Wihl : g_Wal;
    float* C = MODE ? g_gates : g_att;

    wmma::fragment<wmma::accumulator, 16, 16, 16, float> acc[FM][FN];
    #pragma unroll
    for (int i = 0; i < FM; i++)
        #pragma unroll
        for (int j = 0; j < FN; j++)
            wmma::fill_fragment(acc[i][j], 0.0f);

    // ---- async loader for chunk kc into stage s ----
    auto load_chunk = [&](int kc, int s) {
        const __nv_bfloat16 *Ah, *Al, *Wh, *Wl;
        int lda, ka;
        if (MODE == 0 || kc < K1 / KCH) {
            Ah = A1h; Al = A1l; Wh = W1h; Wl = W1l; lda = K1; ka = kc * KCH;
        } else {
            Ah = g_hh_; Al = g_hl_; Wh = g_Whhh; Wl = g_Whhl; lda = K2; ka = (kc - K1/KCH) * KCH;
        }
        const uint32_t st = sb + s * SS;
        #pragma unroll
        for (int it = 0; it < BM*8/256; it++) {
            int idx = tid + it * 256;
            int r = idx >> 3, q = idx & 7;
            size_t src = (size_t)(row0 + r) * lda + ka + q * 8;
            uint32_t off = r * (LDS*2) + q * 16;
            cp16(st + off, Ah + src);
            cp16(st + AOFF + off, Al + src);
        }
        #pragma unroll
        for (int it = 0; it < BN*8/256; it++) {
            int idx = tid + it * 256;
            int r = idx >> 3, q = idx & 7;
            size_t src = (size_t)(col0 + r) * lda + ka + q * 8;
            uint32_t off = r * (LDS*2) + q * 16;
            cp16(st + BOFF + off, Wh + src);
            cp16(st + BLOFF + off, Wl + src);
        }
    };

    load_chunk(0, 0);
    CP_COMMIT();

    for (int kc = 0; kc < NCH; kc++) {
        if (kc + 1 < NCH) { load_chunk(kc + 1, (kc + 1) & 1); CP_COMMIT(); CP_WAIT(1); }
        else              { CP_WAIT(0); }
        __syncthreads();

        const char* st = smem + (kc & 1) * SS;
        const __nv_bfloat16* pAh = (const __nv_bfloat16*)st;
        const __nv_bfloat16* pAl = (const __nv_bfloat16*)(st + AOFF);
        const __nv_bfloat16* pBh = (const __nv_bfloat16*)(st + BOFF);
        const __nv_bfloat16* pBl = (const __nv_bfloat16*)(st + BLOFF);

        #pragma unroll
        for (int k16 = 0; k16 < KCH/16; k16++) {
            const int kk = k16 * 16;
            wmma::fragment<wmma::matrix_a, 16, 16, 16, __nv_bfloat16, wmma::row_major> ah[FM], al[FM];
            wmma::fragment<wmma::matrix_b, 16, 16, 16, __nv_bfloat16, wmma::col_major> bh[FN], bl[FN];
            #pragma unroll
            for (int i = 0; i < FM; i++) {
                int rr = wm * (FM*16) + i * 16;
                wmma::load_matrix_sync(ah[i], pAh + rr * LDS + kk, LDS);
                wmma::load_matrix_sync(al[i], pAl + rr * LDS + kk, LDS);
            }
            #pragma unroll
            for (int j = 0; j < FN; j++) {
                int cc = wn * (FN*16) + j * 16;
                wmma::load_matrix_sync(bh[j], pBh + cc * LDS + kk, LDS);
                wmma::load_matrix_sync(bl[j], pBl + cc * LDS + kk, LDS);
            }
            #pragma unroll
            for (int i = 0; i < FM; i++)
                #pragma unroll
                for (int j = 0; j < FN; j++) {
                    wmma::mma_sync(acc[i][j], ah[i], bh[j], acc[i][j]);
                    wmma::mma_sync(acc[i][j], ah[i], bl[j], acc[i][j]);
                    wmma::mma_sync(acc[i][j], al[i], bh[j], acc[i][j]);
                }
        }
        __syncthreads();
    }

    #pragma unroll
    for (int i = 0; i < FM; i++)
        #pragma unroll
        for (int j = 0; j < FN; j++) {
            int row = row0 + wm * (FM*16) + i * 16;
            int col = col0 + wn * (FN*16) + j * 16;
            wmma::store_matrix_sync(&C[(size_t)row * Ntot + col], acc[i][j], Ntot, wmma::mem_row_major);
        }
}

// ======================= softmax (adds bias) =======================
__global__ void softmax_kernel() {
    int b = blockIdx.x, k = blockIdx.y;
    float* row = &g_att[b * NL + k * Ll];
    int t = threadIdx.x;
    __shared__ float red[256];
    float v = row[t] + g_biasA[k * Ll + t];
    red[t] = v; __syncthreads();
    for (int s = 128; s > 0; s >>= 1) { if (t < s) red[t] = fmaxf(red[t], red[t + s]); __syncthreads(); }
    float m = red[0]; __syncthreads();
    float e = expf(v - m);
    red[t] = e; __syncthreads();
    for (int s = 128; s > 0; s >>= 1) { if (t < s) red[t] += red[t + s]; __syncthreads(); }
    row[t] = e / red[0];
}

// ======================= attention-value (one pass over x), emits split v =======================
__global__ void __launch_bounds__(768, 1) attnv_kernel(const float* __restrict__ x) {
    int b = blockIdx.x;
    int tid = threadIdx.x;            // 768
    int ty = tid / 192, tx = tid % 192;
    __shared__ float a[3][Ll];
    __shared__ float4 part[3][4][192];
    const float* att = &g_att[b * NL];
    for (int i = tid; i < NL; i += 768) a[i >> 8][i & 255] = att[i];
    __syncthreads();
    const float4* xb = (const float4*)(x + (size_t)b * Ll * Dd);
    float4 s1 = {0,0,0,0}, s2 = {0,0,0,0}, s3 = {0,0,0,0};
    int l0 = ty * 64;
    #pragma unroll 4
    for (int l = l0; l < l0 + 64; l++) {
        float4 xv = xb[l * (Dd/4) + tx];
        float w1 = a[0][l], w2 = a[1][l], w3 = a[2][l];
        s1.x += w1*xv.x; s1.y += w1*xv.y; s1.z += w1*xv.z; s1.w += w1*xv.w;
        s2.x += w2*xv.x; s2.y += w2*xv.y; s2.z += w2*xv.z; s2.w += w2*xv.w;
        s3.x += w3*xv.x; s3.y += w3*xv.y; s3.z += w3*xv.z; s3.w += w3*xv.w;
    }
    part[0][ty][tx] = s1; part[1][ty][tx] = s2; part[2][ty][tx] = s3;
    __syncthreads();
    if (tid < 576) {
        int h = tid / 192, j = tid % 192;
        float4 p0 = part[h][0][j], p1 = part[h][1][j], p2 = part[h][2][j], p3 = part[h][3][j];
        float r[4] = { p0.x+p1.x+p2.x+p3.x, p0.y+p1.y+p2.y+p3.y,
                       p0.z+p1.z+p2.z+p3.z, p0.w+p1.w+p2.w+p3.w };
        size_t o = (size_t)b * KV + h * Dd + j * 4;
        #pragma unroll
        for (int u = 0; u < 4; u++) split2(r[u], &g_vh_[o + u], &g_vl_[o + u]);
    }
}

// ======================= LSTM pointwise (adds bias), emits split h =======================
__device__ __forceinline__ float sigmoidf_(float x) { return 1.0f / (1.0f + expf(-x)); }

__global__ void lstm_kernel(float* __restrict__ out, int t_step) {
    int idx = blockIdx.x * blockDim.x + threadIdx.x;  // B*H
    int b = idx >> 10, j = idx & 1023;
    const float* gr = &g_gates[(size_t)b * Gg];
    float ig = gr[j]        + g_biasG[j];
    float fg = gr[Hh + j]   + g_biasG[Hh + j];
    float gg = gr[2*Hh + j] + g_biasG[2*Hh + j];
    float og = gr[3*Hh + j] + g_biasG[3*Hh + j];
    float c = g_c[idx];
    float cn = sigmoidf_(fg) * c + sigmoidf_(ig) * tanhf(gg);
    float hn = sigmoidf_(og) * tanhf(cn);
    g_c[idx] = cn;
    split2(hn, &g_hh_[idx], &g_hl_[idx]);
    out[((size_t)b * Tt + t_step) * Hh + j] = hn;
}

// ======================= driver =======================
extern "C" void kernel_launch(void* const* d_in, const int* in_sizes, int n_in,
                              void* d_out, int out_size) {
    (void)in_sizes; (void)n_in; (void)out_size;
    const float* x    = (const float*)d_in[0];
    const float* h0   = (const float*)d_in[1];
    const float* c0   = (const float*)d_in[2];
    const float* W1   = (const float*)d_in[3];
    const float* b1   = (const float*)d_in[4];
    const float* W2   = (const float*)d_in[5];
    const float* b2   = (const float*)d_in[6];
    const float* W3   = (const float*)d_in[7];
    const float* b3   = (const float*)d_in[8];
    const float* W_ih = (const float*)d_in[9];
    const float* W_hh = (const float*)d_in[10];
    const float* b_ih = (const float*)d_in[11];
    const float* b_hh = (const float*)d_in[12];
    float* out = (float*)d_out;

    const int SMEM1 = (2*128 + 2*64) * LDS * 2 * 2;   // 110592
    const int SMEM0 = (2*64  + 2*64) * LDS * 2 * 2;   // 73728
    cudaFuncSetAttribute(gemm_split_kernel<0>, cudaFuncAttributeMaxDynamicSharedMemorySize, SMEM0);
    cudaFuncSetAttribute(gemm_split_kernel<1>, cudaFuncAttributeMaxDynamicSharedMemorySize, SMEM1);

    __nv_bfloat16 *wah, *wal, *wihh, *wihl, *whhh, *whhl;
    cudaGetSymbolAddress((void**)&wah,  g_Wah);
    cudaGetSymbolAddress((void**)&wal,  g_Wal);
    cudaGetSymbolAddress((void**)&wihh, g_Wihh);
    cudaGetSymbolAddress((void**)&wihl, g_Wihl);
    cudaGetSymbolAddress((void**)&whhh, g_Whhh);
    cudaGetSymbolAddress((void**)&whhl, g_Whhl);

    split_kernel<<<4096, 256>>>(W_ih, wihh, wihl, Gg*KV);
    split_kernel<<<4096, 256>>>(W_hh, whhh, whhl, Gg*Hh);
    split_kernel<<<1024, 256>>>(W1, wah,           wal,           Ll*Hh);
    split_kernel<<<1024, 256>>>(W2, wah + Ll*Hh,   wal + Ll*Hh,   Ll*Hh);
    split_kernel<<<1024, 256>>>(W3, wah + 2*Ll*Hh, wal + 2*Ll*Hh, Ll*Hh);
    bias_prep_kernel<<<16, 256>>>(b_ih, b_hh, b1, b2, b3);
    init_kernel<<<(Bb*Hh + 255)/256, 256>>>(h0, c0);

    for (int t = 0; t < Tt; t++) {
        gemm_split_kernel<0><<<dim3(NL/64, Bb/64), 256, SMEM0>>>();
        softmax_kernel<<<dim3(Bb, 3), 256>>>();
        attnv_kernel<<<Bb, 768>>>(x);
        gemm_split_kernel<1><<<dim3(Gg/64, Bb/128), 256, SMEM1>>>();
        lstm_kernel<<<(Bb*Hh + 255)/256, 256>>>(out, t);
    }
}

// round 8
// speedup vs baseline: 1.2083x; 1.2083x over previous
#include <cuda_runtime.h>
#include <cuda_bf16.h>
#include <mma.h>
#include <cstdint>
#include <math.h>

using namespace nvcuda;

#define Bb 256
#define Ll 256
#define Dd 768
#define Hh 1024
#define Tt 32
#define KV (3*Dd)   // 2304
#define Gg (4*Hh)   // 4096
#define NL (3*Ll)   // 768
#define KCH 64      // K elems per smem chunk
#define LDS 72      // padded smem stride (elems), 144 B

// GEMM tile config: 64x64 CTA tile, 128 threads (4 warps, 2x2), FM=FN=2
#define BMg 64
#define BNg 64
#define SSg ((2*BMg + 2*BNg) * LDS * 2)     // 36864 B per stage
#define AOFFg (BMg * LDS * 2)
#define BOFFg (2 * BMg * LDS * 2)
#define BLOFFg (BOFFg + BNg * LDS * 2)
#define SMEMg (2 * SSg)                      // 73728

// ======================= device scratch =======================
__device__ float g_c[Bb*Hh];
__device__ float g_att[Bb*NL];
__device__ float g_gates[Bb*Gg];          // hh partial, gate-interleaved cols
__device__ float g_biasG[Gg];             // reordered: [unit*4+gate]
__device__ float g_biasA[NL];
__device__ __align__(16) __nv_bfloat16 g_hh_[Bb*Hh], g_hl_[Bb*Hh];
__device__ __align__(16) __nv_bfloat16 g_vh_[Bb*KV], g_vl_[Bb*KV];
__device__ __align__(16) __nv_bfloat16 g_Wah[NL*Hh],  g_Wal[NL*Hh];
__device__ __align__(16) __nv_bfloat16 g_Wihh[Gg*KV], g_Wihl[Gg*KV];   // rows reordered
__device__ __align__(16) __nv_bfloat16 g_Whhh[Gg*Hh], g_Whhl[Gg*Hh];   // rows reordered

__device__ __forceinline__ void split2(float a, __nv_bfloat16* hi, __nv_bfloat16* lo) {
    __nv_bfloat16 h = __float2bfloat16_rn(a);
    *hi = h;
    *lo = __float2bfloat16_rn(a - __bfloat162float(h));
}
__device__ __forceinline__ uint32_t smem_u32(const void* p) {
    uint32_t a;
    asm("{ .reg .u64 t; cvta.to.shared.u64 t, %1; cvt.u32.u64 %0, t; }" : "=r"(a) : "l"(p));
    return a;
}
__device__ __forceinline__ void cp16(uint32_t s, const void* g) {
    asm volatile("cp.async.cg.shared.global [%0], [%1], 16;" :: "r"(s), "l"(g));
}
#define CP_COMMIT() asm volatile("cp.async.commit_group;" ::: "memory")
#define CP_WAIT(n)  asm volatile("cp.async.wait_group %0;" :: "n"(n) : "memory")
__device__ __forceinline__ float sigmoidf_(float x) { return 1.0f / (1.0f + expf(-x)); }

// ======================= prep kernels =======================
__global__ void split_kernel(const float* __restrict__ src, __nv_bfloat16* __restrict__ hi,
                             __nv_bfloat16* __restrict__ lo, int n) {
    for (int i = blockIdx.x * blockDim.x + threadIdx.x; i < n; i += gridDim.x * blockDim.x)
        split2(src[i], &hi[i], &lo[i]);
}

// split + gate-interleave row reorder: orig row r = gate*1024+unit -> r' = unit*4+gate
__global__ void split_reorder_kernel(const float* __restrict__ src, __nv_bfloat16* __restrict__ hi,
                                     __nv_bfloat16* __restrict__ lo, int K, int n) {
    for (int i = blockIdx.x * blockDim.x + threadIdx.x; i < n; i += gridDim.x * blockDim.x) {
        int r = i / K, k = i - r * K;
        int gate = r >> 10, unit = r & 1023;
        size_t dst = (size_t)(unit * 4 + gate) * K + k;
        split2(src[i], &hi[dst], &lo[dst]);
    }
}

__global__ void bias_prep_kernel(const float* __restrict__ b_ih, const float* __restrict__ b_hh,
                                 const float* __restrict__ b1, const float* __restrict__ b2,
                                 const float* __restrict__ b3) {
    int j = blockIdx.x * blockDim.x + threadIdx.x;
    if (j < Gg) {
        int gate = j >> 10, unit = j & 1023;
        g_biasG[unit * 4 + gate] = b_ih[j] + b_hh[j];
    }
    if (j < NL) g_biasA[j] = (j < Ll) ? b1[j] : (j < 2*Ll) ? b2[j - Ll] : b3[j - 2*Ll];
}

__global__ void init_kernel(const float* __restrict__ h0, const float* __restrict__ c0) {
    int i = blockIdx.x * blockDim.x + threadIdx.x;
    if (i < Bb*Hh) { split2(h0[i], &g_hh_[i], &g_hl_[i]); g_c[i] = c0[i]; }
}

// ======================= GEMM mainloop core (64x64 tile, 128 thr) =======================
// Computes acc = (Ah+Al)[row0:+64, :K] @ (Wh+Wl)[col0:+64, :K]^T  (3-term split)
template <int NCH>
__device__ __forceinline__ void gemm_core(
    char* smem, uint32_t sb, int tid,
    const __nv_bfloat16* __restrict__ Ah, const __nv_bfloat16* __restrict__ Al,
    const __nv_bfloat16* __restrict__ Wh, const __nv_bfloat16* __restrict__ Wl,
    int K, int row0, int col0,
    wmma::fragment<wmma::accumulator, 16, 16, 16, float> (&acc)[2][2],
    int wm, int wn)
{
    auto load_chunk = [&](int kc, int s) {
        const int ka = kc * KCH;
        const uint32_t st = sb + s * SSg;
        #pragma unroll
        for (int it = 0; it < 4; it++) {
            int idx = tid + it * 128, r = idx >> 3, q = idx & 7;
            size_t src = (size_t)(row0 + r) * K + ka + q * 8;
            uint32_t off = r * (LDS*2) + q * 16;
            cp16(st + off, Ah + src);
            cp16(st + AOFFg + off, Al + src);
        }
        #pragma unroll
        for (int it = 0; it < 4; it++) {
            int idx = tid + it * 128, r = idx >> 3, q = idx & 7;
            size_t src = (size_t)(col0 + r) * K + ka + q * 8;
            uint32_t off = r * (LDS*2) + q * 16;
            cp16(st + BOFFg + off, Wh + src);
            cp16(st + BLOFFg + off, Wl + src);
        }
    };

    load_chunk(0, 0); CP_COMMIT();
    for (int kc = 0; kc < NCH; kc++) {
        if (kc + 1 < NCH) { load_chunk(kc + 1, (kc + 1) & 1); CP_COMMIT(); CP_WAIT(1); }
        else              { CP_WAIT(0); }
        __syncthreads();
        const char* st = smem + (kc & 1) * SSg;
        const __nv_bfloat16* pAh = (const __nv_bfloat16*)st;
        const __nv_bfloat16* pAl = (const __nv_bfloat16*)(st + AOFFg);
        const __nv_bfloat16* pBh = (const __nv_bfloat16*)(st + BOFFg);
        const __nv_bfloat16* pBl = (const __nv_bfloat16*)(st + BLOFFg);
        #pragma unroll
        for (int k16 = 0; k16 < KCH/16; k16++) {
            const int kk = k16 * 16;
            wmma::fragment<wmma::matrix_a, 16, 16, 16, __nv_bfloat16, wmma::row_major> ah[2], al[2];
            wmma::fragment<wmma::matrix_b, 16, 16, 16, __nv_bfloat16, wmma::col_major> bh[2], bl[2];
            #pragma unroll
            for (int i = 0; i < 2; i++) {
                int rr = wm * 32 + i * 16;
                wmma::load_matrix_sync(ah[i], pAh + rr * LDS + kk, LDS);
                wmma::load_matrix_sync(al[i], pAl + rr * LDS + kk, LDS);
            }
            #pragma unroll
            for (int j = 0; j < 2; j++) {
                int cc = wn * 32 + j * 16;
                wmma::load_matrix_sync(bh[j], pBh + cc * LDS + kk, LDS);
                wmma::load_matrix_sync(bl[j], pBl + cc * LDS + kk, LDS);
            }
            #pragma unroll
            for (int i = 0; i < 2; i++)
                #pragma unroll
                for (int j = 0; j < 2; j++) {
                    wmma::mma_sync(acc[i][j], ah[i], bh[j], acc[i][j]);
                    wmma::mma_sync(acc[i][j], ah[i], bl[j], acc[i][j]);
                    wmma::mma_sync(acc[i][j], al[i], bh[j], acc[i][j]);
                }
        }
        __syncthreads();
    }
}

// ======================= fused launch A: logits + gates_hh (both A=h, K=1024) ==========
// grid 304 CTAs x 128 thr: bid<48 -> logits tile, else gates_hh tile.
__global__ void __launch_bounds__(128) fusedA_kernel() {
    extern __shared__ __align__(16) char smem[];
    const uint32_t sb = smem_u32(smem);
    const int tid = threadIdx.x, wid = tid >> 5, wm = wid >> 1, wn = wid & 1;
    const int bid = blockIdx.x;

    const bool isLog = bid < 48;
    int m_t, n_t;
    const __nv_bfloat16 *Wh, *Wl;
    float* C;
    int Nt;
    if (isLog) {
        m_t = bid & 3; n_t = bid >> 2;          // 0..11
        Wh = g_Wah; Wl = g_Wal; C = g_att; Nt = NL;
    } else {
        int b2 = bid - 48;
        m_t = b2 & 3; n_t = b2 >> 2;            // 0..63
        Wh = g_Whhh; Wl = g_Whhl; C = g_gates; Nt = Gg;
    }
    const int row0 = m_t * BMg, col0 = n_t * BNg;

    wmma::fragment<wmma::accumulator, 16, 16, 16, float> acc[2][2];
    #pragma unroll
    for (int i = 0; i < 2; i++) for (int j = 0; j < 2; j++) wmma::fill_fragment(acc[i][j], 0.0f);

    gemm_core<Hh/KCH>(smem, sb, tid, g_hh_, g_hl_, Wh, Wl, Hh, row0, col0, acc, wm, wn);

    #pragma unroll
    for (int i = 0; i < 2; i++)
        #pragma unroll
        for (int j = 0; j < 2; j++) {
            int row = row0 + wm * 32 + i * 16;
            int col = col0 + wn * 32 + j * 16;
            wmma::store_matrix_sync(&C[(size_t)row * Nt + col], acc[i][j], Nt, wmma::mem_row_major);
        }
}

// ======================= gates_ih + fused LSTM (A=v, K=2304) =======================
__global__ void __launch_bounds__(128) gates_ih_kernel(float* __restrict__ out, int t_step) {
    extern __shared__ __align__(16) char smem[];
    const uint32_t sb = smem_u32(smem);
    const int tid = threadIdx.x, wid = tid >> 5, wm = wid >> 1, wn = wid & 1;
    const int bid = blockIdx.x;                 // 256 CTAs
    const int m_t = bid & 3, n_t = bid >> 2;    // n_t 0..63
    const int row0 = m_t * BMg, col0 = n_t * BNg;

    wmma::fragment<wmma::accumulator, 16, 16, 16, float> acc[2][2];
    #pragma unroll
    for (int i = 0; i < 2; i++) for (int j = 0; j < 2; j++) wmma::fill_fragment(acc[i][j], 0.0f);

    gemm_core<KV/KCH>(smem, sb, tid, g_vh_, g_vl_, g_Wihh, g_Wihl, KV, row0, col0, acc, wm, wn);

    // stage acc tile (64 x 64, stride 68) then fused LSTM epilogue
    float* smf = (float*)smem;
    #pragma unroll
    for (int i = 0; i < 2; i++)
        #pragma unroll
        for (int j = 0; j < 2; j++)
            wmma::store_matrix_sync(smf + (wm*32 + i*16) * 68 + (wn*32 + j*16),
                                    acc[i][j], 68, wmma::mem_row_major);
    __syncthreads();

    const int unit0 = n_t * 16;                 // 16 hidden units per CTA (4 gates each)
    #pragma unroll
    for (int it = 0; it < 8; it++) {
        int idx = tid + it * 128;               // 0..1023
        int r = idx >> 4, u = idx & 15;
        int row = row0 + r, j = unit0 + u;
        float4 av = *(const float4*)&smf[r * 68 + u * 4];
        float4 pv = *(const float4*)&g_gates[(size_t)row * Gg + n_t * 64 + u * 4];
        float4 bv = *(const float4*)&g_biasG[n_t * 64 + u * 4];
        float ig = av.x + pv.x + bv.x;
        float fg = av.y + pv.y + bv.y;
        float gg = av.z + pv.z + bv.z;
        float og = av.w + pv.w + bv.w;
        int ci = row * Hh + j;
        float c = g_c[ci];
        float cn = sigmoidf_(fg) * c + sigmoidf_(ig) * tanhf(gg);
        float hn = sigmoidf_(og) * tanhf(cn);
        g_c[ci] = cn;
        split2(hn, &g_hh_[ci], &g_hl_[ci]);
        out[((size_t)row * Tt + t_step) * Hh + j] = hn;
    }
}

// ======================= fused softmax + attention-value =======================
__global__ void __launch_bounds__(768, 1) attnv_kernel(const float* __restrict__ x) {
    int b = blockIdx.x;
    int tid = threadIdx.x;
    __shared__ float a[3][Ll];
    __shared__ float4 part[3][4][192];
    __shared__ float red[3][8];

    // --- softmax over each of 3 rows of 256 logits (bias added here) ---
    {
        int h = tid >> 8, j = tid & 255;
        float v = g_att[b * NL + h * 256 + j] + g_biasA[h * 256 + j];
        float m = v;
        #pragma unroll
        for (int o = 16; o; o >>= 1) m = fmaxf(m, __shfl_xor_sync(0xffffffffu, m, o));
        int w8 = (tid >> 5) & 7;
        if ((tid & 31) == 0) red[h][w8] = m;
        __syncthreads();
        float mm = red[h][0];
        #pragma unroll
        for (int q = 1; q < 8; q++) mm = fmaxf(mm, red[h][q]);
        float e = expf(v - mm);
        float s = e;
        #pragma unroll
        for (int o = 16; o; o >>= 1) s += __shfl_xor_sync(0xffffffffu, s, o);
        __syncthreads();
        if ((tid & 31) == 0) red[h][w8] = s;
        __syncthreads();
        float ss = red[h][0];
        #pragma unroll
        for (int q = 1; q < 8; q++) ss += red[h][q];
        a[h][j] = e / ss;
    }
    __syncthreads();

    // --- v_k = sum_l a_k[l] * x[b,l,:], L split 4-way ---
    int ty = tid / 192, tx = tid % 192;
    const float4* xb = (const float4*)(x + (size_t)b * Ll * Dd);
    float4 s1 = {0,0,0,0}, s2 = {0,0,0,0}, s3 = {0,0,0,0};
    int l0 = ty * 64;
    #pragma unroll 4
    for (int l = l0; l < l0 + 64; l++) {
        float4 xv = xb[l * (Dd/4) + tx];
        float w1 = a[0][l], w2 = a[1][l], w3 = a[2][l];
        s1.x += w1*xv.x; s1.y += w1*xv.y; s1.z += w1*xv.z; s1.w += w1*xv.w;
        s2.x += w2*xv.x; s2.y += w2*xv.y; s2.z += w2*xv.z; s2.w += w2*xv.w;
        s3.x += w3*xv.x; s3.y += w3*xv.y; s3.z += w3*xv.z; s3.w += w3*xv.w;
    }
    part[0][ty][tx] = s1; part[1][ty][tx] = s2; part[2][ty][tx] = s3;
    __syncthreads();
    if (tid < 576) {
        int h = tid / 192, j = tid % 192;
        float4 p0 = part[h][0][j], p1 = part[h][1][j], p2 = part[h][2][j], p3 = part[h][3][j];
        float r[4] = { p0.x+p1.x+p2.x+p3.x, p0.y+p1.y+p2.y+p3.y,
                       p0.z+p1.z+p2.z+p3.z, p0.w+p1.w+p2.w+p3.w };
        size_t o = (size_t)b * KV + h * Dd + j * 4;
        #pragma unroll
        for (int u = 0; u < 4; u++) split2(r[u], &g_vh_[o + u], &g_vl_[o + u]);
    }
}

// ======================= driver (single stream, graph-safe) =======================
extern "C" void kernel_launch(void* const* d_in, const int* in_sizes, int n_in,
                              void* d_out, int out_size) {
    (void)in_sizes; (void)n_in; (void)out_size;
    const float* x    = (const float*)d_in[0];
    const float* h0   = (const float*)d_in[1];
    const float* c0   = (const float*)d_in[2];
    const float* W1   = (const float*)d_in[3];
    const float* b1   = (const float*)d_in[4];
    const float* W2   = (const float*)d_in[5];
    const float* b2   = (const float*)d_in[6];
    const float* W3   = (const float*)d_in[7];
    const float* b3   = (const float*)d_in[8];
    const float* W_ih = (const float*)d_in[9];
    const float* W_hh = (const float*)d_in[10];
    const float* b_ih = (const float*)d_in[11];
    const float* b_hh = (const float*)d_in[12];
    float* out = (float*)d_out;

    cudaFuncSetAttribute(fusedA_kernel,   cudaFuncAttributeMaxDynamicSharedMemorySize, SMEMg);
    cudaFuncSetAttribute(gates_ih_kernel, cudaFuncAttributeMaxDynamicSharedMemorySize, SMEMg);

    __nv_bfloat16 *wah, *wal, *wihh, *wihl, *whhh, *whhl;
    cudaGetSymbolAddress((void**)&wah,  g_Wah);
    cudaGetSymbolAddress((void**)&wal,  g_Wal);
    cudaGetSymbolAddress((void**)&wihh, g_Wihh);
    cudaGetSymbolAddress((void**)&wihl, g_Wihl);
    cudaGetSymbolAddress((void**)&whhh, g_Whhh);
    cudaGetSymbolAddress((void**)&whhl, g_Whhl);

    split_reorder_kernel<<<4096, 256>>>(W_ih, wihh, wihl, KV, Gg*KV);
    split_reorder_kernel<<<4096, 256>>>(W_hh, whhh, whhl, Hh, Gg*Hh);
    split_kernel<<<1024, 256>>>(W1, wah,           wal,           Ll*Hh);
    split_kernel<<<1024, 256>>>(W2, wah + Ll*Hh,   wal + Ll*Hh,   Ll*Hh);
    split_kernel<<<1024, 256>>>(W3, wah + 2*Ll*Hh, wal + 2*Ll*Hh, Ll*Hh);
    bias_prep_kernel<<<16, 256>>>(b_ih, b_hh, b1, b2, b3);
    init_kernel<<<(Bb*Hh + 255)/256, 256>>>(h0, c0);

    for (int t = 0; t < Tt; t++) {
        fusedA_kernel<<<304, 128, SMEMg>>>();              // logits + gates_hh (indep. of attn)
        attnv_kernel<<<Bb, 768>>>(x);                      // softmax + value gather
        gates_ih_kernel<<<256, 128, SMEMg>>>(out, t);      // ih GEMM + LSTM epilogue
    }
}